// round 4
// baseline (speedup 1.0000x reference)
#include <cuda_runtime.h>
#include <math.h>

// Problem constants
#define MTOT 32768      // B*T = 8*4096
#define DIN  512        // D
#define DC   256        // Dc
#define NQ   8
#define BINS 1024
#define RVQ_BLOCKS (MTOT / 128)   // 256

#define OUT_ELEMS   ((size_t)MTOT * DIN)        // 16777216
#define IDX_ELEMS   ((size_t)NQ * MTOT)         // 262144

// Scratch (static device globals; allocation-free), 256B aligned for float4.
__device__ __align__(256) float  g_h[MTOT * DC];       // 32 MB
__device__ __align__(256) float  g_res[MTOT * DC];     // 32 MB
__device__ __align__(256) float  g_q[MTOT * DC];       // 32 MB (sum of gathered codewords)
__device__ __align__(256) float  g_e2[NQ * BINS];
__device__ __align__(256) double g_partial[NQ * RVQ_BLOCKS];
__device__ __align__(256) float  g_idx_sink[IDX_ELEMS];
__device__ __align__(256) float  g_commit_sink[16];

// ---------------------------------------------------------------------------
// XLA/Eigen rational tanh for f32 (what jnp.tanh lowers to on GPU):
// |x| < 0.0004 -> x ; clamp to [-9, 9]; x*P(x^2)/Q(x^2).
// Polynomials evaluated with separate mul/add (LLVM default: no contraction).
// ---------------------------------------------------------------------------
__device__ __forceinline__ float xla_tanh(float x) {
    float ax = fabsf(x);
    float xc = fminf(fmaxf(x, -9.0f), 9.0f);
    float x2 = __fmul_rn(xc, xc);
    float p = -2.76076847742355e-16f;
    p = __fadd_rn(__fmul_rn(p, x2),  2.00018790482477e-13f);
    p = __fadd_rn(__fmul_rn(p, x2), -8.60467152213735e-11f);
    p = __fadd_rn(__fmul_rn(p, x2),  5.12229709037114e-08f);
    p = __fadd_rn(__fmul_rn(p, x2),  1.48572235717979e-05f);
    p = __fadd_rn(__fmul_rn(p, x2),  6.37261928875436e-04f);
    p = __fadd_rn(__fmul_rn(p, x2),  4.89352455891786e-03f);
    float num = __fmul_rn(xc, p);
    float q = 1.19825839466702e-06f;
    q = __fadd_rn(__fmul_rn(q, x2), 1.18534705686654e-04f);
    q = __fadd_rn(__fmul_rn(q, x2), 2.26843463243900e-03f);
    q = __fadd_rn(__fmul_rn(q, x2), 4.89352518554385e-03f);
    float r = __fdiv_rn(num, q);
    return (ax < 0.0004f) ? x : r;
}

// ---------------------------------------------------------------------------
// XLA-style warp row reduction: lane l sums elements l, l+32, ... (ascending),
// then shfl_down tree 16,8,4,2,1; result in lane 0. All fp32 mul+add (no fma).
// ---------------------------------------------------------------------------
__device__ __forceinline__ float warp_rowsum_sq(const float* __restrict__ p, int lane) {
    float s = 0.f;
    #pragma unroll
    for (int t = 0; t < DC / 32; t++) {
        float v = p[lane + 32 * t];
        s = __fadd_rn(s, __fmul_rn(v, v));
    }
    #pragma unroll
    for (int o = 16; o; o >>= 1)
        s = __fadd_rn(s, __shfl_down_sync(0xffffffffu, s, o));
    return s;
}

// e2[n*BINS+b] = ||codebook[n][b]||^2  (fp32, XLA row-reduce pattern)
__global__ void e2_kernel(const float* __restrict__ cb) {
    int warp = (blockIdx.x * blockDim.x + threadIdx.x) >> 5;
    int lane = threadIdx.x & 31;
    int nwarps = (gridDim.x * blockDim.x) >> 5;
    for (int row = warp; row < NQ * BINS; row += nwarps) {
        float s = warp_rowsum_sq(cb + (size_t)row * DC, lane);
        if (lane == 0) g_e2[row] = s;
    }
}

// ---------------------------------------------------------------------------
// proj_in: h = xla_tanh(x @ in_w^T + in_b); serial fp32 k-ascending FFMA
// chain per accumulator (bit-matches cublas/triton). Also zeroes g_q.
// 128x128x16, 256 threads, 8x8 microtile.
// ---------------------------------------------------------------------------
__global__ __launch_bounds__(256, 2)
void proj_in_kernel(const float* __restrict__ A,
                    const float* __restrict__ Bw,
                    const float* __restrict__ bias) {
    __shared__ float As[16][128];
    __shared__ float Bs[16][128];

    int tid = threadIdx.x;
    int tx = tid & 15, ty = tid >> 4;
    int rowBase = blockIdx.x * 128;
    int colBase = blockIdx.y * 128;

    float acc[8][8];
    #pragma unroll
    for (int i = 0; i < 8; i++)
        #pragma unroll
        for (int j = 0; j < 8; j++) acc[i][j] = 0.f;

    for (int kc = 0; kc < DIN; kc += 16) {
        #pragma unroll
        for (int l = 0; l < 2; l++) {
            int id = tid + l * 256;
            int r = id >> 2, kq = (id & 3) * 4;
            float4 v = *(const float4*)(A + (size_t)(rowBase + r) * DIN + kc + kq);
            As[kq + 0][r] = v.x; As[kq + 1][r] = v.y;
            As[kq + 2][r] = v.z; As[kq + 3][r] = v.w;
            float4 b = *(const float4*)(Bw + (size_t)(colBase + r) * DIN + kc + kq);
            Bs[kq + 0][r] = b.x; Bs[kq + 1][r] = b.y;
            Bs[kq + 2][r] = b.z; Bs[kq + 3][r] = b.w;
        }
        __syncthreads();
        #pragma unroll
        for (int kk = 0; kk < 16; kk++) {
            float a[8], b[8];
            #pragma unroll
            for (int i = 0; i < 8; i++) a[i] = As[kk][ty * 8 + i];
            #pragma unroll
            for (int j = 0; j < 8; j++) b[j] = Bs[kk][tx * 8 + j];
            #pragma unroll
            for (int i = 0; i < 8; i++)
                #pragma unroll
                for (int j = 0; j < 8; j++) acc[i][j] = fmaf(a[i], b[j], acc[i][j]);
        }
        __syncthreads();
    }

    #pragma unroll
    for (int i = 0; i < 8; i++) {
        int row = rowBase + ty * 8 + i;
        #pragma unroll
        for (int j = 0; j < 8; j++) {
            int col = colBase + tx * 8 + j;
            float pre = __fadd_rn(acc[i][j], bias[col]);   // gemm then +b (separate HLO)
            float t = xla_tanh(pre);                       // * CODEC_RANGE (=1.0)
            size_t off = (size_t)row * DC + col;
            g_h[off] = t;
            g_res[off] = t;
        }
    }
}

// ---------------------------------------------------------------------------
// lexicographic (value, index) min — exact total order, pairing-invariant
// ---------------------------------------------------------------------------
__device__ __forceinline__ void amin_merge(float& bv, int& bi, float v, int i) {
    if (v < bv || (v == bv && i < bi)) { bv = v; bi = i; }
}

// ---------------------------------------------------------------------------
// One RVQ step. dist = (r2 - 2*re) + e2, fp32, matching reference's
// elementwise form; re via serial k-ascending FFMA chain; fp32 argmin.
// ---------------------------------------------------------------------------
__global__ __launch_bounds__(256, 2)
void rvq_step_kernel(const float* __restrict__ cb_all, int step,
                     float* __restrict__ idx_out) {
    const float* cb = cb_all + (size_t)step * BINS * DC;
    const float* e2 = g_e2 + step * BINS;

    __shared__ float As[16][128];
    __shared__ float Bs[16][128];
    __shared__ float r2row[128];
    __shared__ float candV[128];
    __shared__ int   candI[128];
    __shared__ float bestV[128];
    __shared__ int   bestI[128];
    __shared__ double rs[256];

    int tid = threadIdx.x;
    int tx = tid & 15, ty = tid >> 4;
    int wid = tid >> 5, lane = tid & 31;
    int rowBase = blockIdx.x * 128;

    // r2 per row (XLA row-reduce pattern), 8 warps x 16 rows
    for (int r = wid * 16; r < wid * 16 + 16; r++) {
        float s = warp_rowsum_sq(g_res + (size_t)(rowBase + r) * DC, lane);
        if (lane == 0) r2row[r] = s;
    }
    if (tid < 128) { bestV[tid] = 3.4e38f; bestI[tid] = 0x7fffffff; }
    __syncthreads();

    for (int bc = 0; bc < BINS; bc += 128) {
        float acc[8][8];
        #pragma unroll
        for (int i = 0; i < 8; i++)
            #pragma unroll
            for (int j = 0; j < 8; j++) acc[i][j] = 0.f;

        for (int kc = 0; kc < DC; kc += 16) {
            #pragma unroll
            for (int l = 0; l < 2; l++) {
                int id = tid + l * 256;
                int r = id >> 2, kq = (id & 3) * 4;
                float4 v = *(const float4*)(g_res + (size_t)(rowBase + r) * DC + kc + kq);
                As[kq + 0][r] = v.x; As[kq + 1][r] = v.y;
                As[kq + 2][r] = v.z; As[kq + 3][r] = v.w;
                float4 b = *(const float4*)(cb + (size_t)(bc + r) * DC + kc + kq);
                Bs[kq + 0][r] = b.x; Bs[kq + 1][r] = b.y;
                Bs[kq + 2][r] = b.z; Bs[kq + 3][r] = b.w;
            }
            __syncthreads();
            #pragma unroll
            for (int kk = 0; kk < 16; kk++) {
                float a[8], b[8];
                #pragma unroll
                for (int i = 0; i < 8; i++) a[i] = As[kk][ty * 8 + i];
                #pragma unroll
                for (int j = 0; j < 8; j++) b[j] = Bs[kk][tx * 8 + j];
                #pragma unroll
                for (int i = 0; i < 8; i++)
                    #pragma unroll
                    for (int j = 0; j < 8; j++) acc[i][j] = fmaf(a[i], b[j], acc[i][j]);
            }
            __syncthreads();
        }

        float ee[8];
        #pragma unroll
        for (int j = 0; j < 8; j++) ee[j] = e2[bc + tx * 8 + j];

        #pragma unroll
        for (int i = 0; i < 8; i++) {
            int row = ty * 8 + i;
            float r2 = r2row[row];
            float bv = 3.4e38f; int bi = 0x7fffffff;
            #pragma unroll
            for (int j = 0; j < 8; j++) {
                // (r2 - 2*re) + e2, non-contracted, matching XLA elementwise
                float d = __fadd_rn(__fsub_rn(r2, __fmul_rn(2.0f, acc[i][j])), ee[j]);
                amin_merge(bv, bi, d, bc + tx * 8 + j);
            }
            #pragma unroll
            for (int m = 1; m <= 8; m <<= 1) {
                float ov = __shfl_xor_sync(0xffffffffu, bv, m);
                int   oi = __shfl_xor_sync(0xffffffffu, bi, m);
                amin_merge(bv, bi, ov, oi);
            }
            if (tx == 0) { candV[row] = bv; candI[row] = bi; }
        }
        __syncthreads();
        if (tid < 128) {
            float bv = bestV[tid]; int bi = bestI[tid];
            amin_merge(bv, bi, candV[tid], candI[tid]);
            bestV[tid] = bv; bestI[tid] = bi;
        }
        __syncthreads();
    }

    if (tid < 128)
        idx_out[(size_t)step * MTOT + rowBase + tid] = (float)bestI[tid];

    // gather + residual update + q accumulation + commit partial
    double csum = 0.0;
    for (int r = 0; r < 128; r++) {
        int gi = bestI[r];
        float c = cb[(size_t)gi * DC + tid];
        size_t off = (size_t)(rowBase + r) * DC + tid;
        float old = g_res[off];
        float t = __fsub_rn(c, old);                 // q - residual (commit term)
        csum += (double)__fmul_rn(t, t);
        g_res[off] = __fsub_rn(old, c);              // residual - q
        g_q[off] = (step == 0) ? c : __fadd_rn(g_q[off], c);   // n-ascending sum
    }
    rs[tid] = csum;
    __syncthreads();
    #pragma unroll
    for (int s = 128; s; s >>= 1) {
        if (tid < s) rs[tid] += rs[tid + s];
        __syncthreads();
    }
    if (tid == 0) g_partial[step * RVQ_BLOCKS + blockIdx.x] = rs[0];
}

// ---------------------------------------------------------------------------
// commit_loss = 0.1 * sum_n mean(res_n^2)   (fp64, deterministic)
// ---------------------------------------------------------------------------
__global__ void finalize_kernel(float* __restrict__ commit_out) {
    if (blockIdx.x == 0 && threadIdx.x == 0) {
        double total = 0.0;
        for (int n = 0; n < NQ; n++) {
            double s = 0.0;
            for (int b = 0; b < RVQ_BLOCKS; b++) s += g_partial[n * RVQ_BLOCKS + b];
            total += s / ((double)MTOT * (double)DC);
        }
        *commit_out = (float)(0.1 * total);
    }
}

// ---------------------------------------------------------------------------
// proj_out: out = (h + (sumq - h)) @ out_w^T + out_b  (STE form, fp32)
// ---------------------------------------------------------------------------
__global__ __launch_bounds__(256, 2)
void proj_out_kernel(const float* __restrict__ Bw,
                     const float* __restrict__ bias,
                     float* __restrict__ C) {
    __shared__ float As[16][128];
    __shared__ float Bs[16][128];

    int tid = threadIdx.x;
    int tx = tid & 15, ty = tid >> 4;
    int rowBase = blockIdx.x * 128;
    int colBase = blockIdx.y * 128;

    float acc[8][8];
    #pragma unroll
    for (int i = 0; i < 8; i++)
        #pragma unroll
        for (int j = 0; j < 8; j++) acc[i][j] = 0.f;

    for (int kc = 0; kc < DC; kc += 16) {
        #pragma unroll
        for (int l = 0; l < 2; l++) {
            int id = tid + l * 256;
            int r = id >> 2, kq = (id & 3) * 4;
            size_t off = (size_t)(rowBase + r) * DC + kc + kq;
            float4 h4 = *(const float4*)(g_h + off);
            float4 q4 = *(const float4*)(g_q + off);
            // quantized = h + (sumq - h), elementwise, non-contracted
            As[kq + 0][r] = __fadd_rn(h4.x, __fsub_rn(q4.x, h4.x));
            As[kq + 1][r] = __fadd_rn(h4.y, __fsub_rn(q4.y, h4.y));
            As[kq + 2][r] = __fadd_rn(h4.z, __fsub_rn(q4.z, h4.z));
            As[kq + 3][r] = __fadd_rn(h4.w, __fsub_rn(q4.w, h4.w));
            float4 b = *(const float4*)(Bw + (size_t)(colBase + r) * DC + kc + kq);
            Bs[kq + 0][r] = b.x; Bs[kq + 1][r] = b.y;
            Bs[kq + 2][r] = b.z; Bs[kq + 3][r] = b.w;
        }
        __syncthreads();
        #pragma unroll
        for (int kk = 0; kk < 16; kk++) {
            float a[8], b[8];
            #pragma unroll
            for (int i = 0; i < 8; i++) a[i] = As[kk][ty * 8 + i];
            #pragma unroll
            for (int j = 0; j < 8; j++) b[j] = Bs[kk][tx * 8 + j];
            #pragma unroll
            for (int i = 0; i < 8; i++)
                #pragma unroll
                for (int j = 0; j < 8; j++) acc[i][j] = fmaf(a[i], b[j], acc[i][j]);
        }
        __syncthreads();
    }

    #pragma unroll
    for (int i = 0; i < 8; i++) {
        int row = rowBase + ty * 8 + i;
        #pragma unroll
        for (int j = 0; j < 8; j++) {
            int col = colBase + tx * 8 + j;
            C[(size_t)row * DIN + col] = __fadd_rn(acc[i][j], bias[col]);
        }
    }
}

// ---------------------------------------------------------------------------
extern "C" void kernel_launch(void* const* d_in, const int* in_sizes, int n_in,
                              void* d_out, int out_size) {
    const float* x     = (const float*)d_in[0];   // [8,4096,512]
    const float* in_w  = (const float*)d_in[1];   // [256,512]
    const float* in_b  = (const float*)d_in[2];   // [256]
    const float* out_w = (const float*)d_in[3];   // [512,256]
    const float* out_b = (const float*)d_in[4];   // [512]
    const float* cb    = (const float*)d_in[5];   // [8,1024,256]

    float* out_f = (float*)d_out;

    // Decide output layout defensively from out_size; never write past d_out.
    float* idx_f    = nullptr;
    float* commit_f = nullptr;
    if ((size_t)out_size >= OUT_ELEMS + IDX_ELEMS + 1) {
        idx_f    = out_f + OUT_ELEMS;
        commit_f = out_f + OUT_ELEMS + IDX_ELEMS;
    } else if ((size_t)out_size >= OUT_ELEMS + IDX_ELEMS) {
        idx_f = out_f + OUT_ELEMS;
    }
    if (!idx_f)    cudaGetSymbolAddress((void**)&idx_f,    g_idx_sink);
    if (!commit_f) cudaGetSymbolAddress((void**)&commit_f, g_commit_sink);

    e2_kernel<<<64, 256>>>(cb);

    {
        dim3 grid(MTOT / 128, DC / 128);
        proj_in_kernel<<<grid, 256>>>(x, in_w, in_b);
    }

    for (int n = 0; n < NQ; n++)
        rvq_step_kernel<<<RVQ_BLOCKS, 256>>>(cb, n, idx_f);

    finalize_kernel<<<1, 32>>>(commit_f);

    {
        dim3 grid(MTOT / 128, DIN / 128);
        proj_out_kernel<<<grid, 256>>>(out_w, out_b, out_f);
    }
}